// round 2
// baseline (speedup 1.0000x reference)
#include <cuda_runtime.h>
#include <math_constants.h>

// Problem shape (fixed by the dataset)
#define BATCH   16
#define CDIM    256
#define HWDIM   1024          // 32*32
#define N_TOK   16384         // BATCH * HWDIM
#define K_CODES 8192

#define ZQ_ELEMS (BATCH * CDIM * HWDIM)   // 4194304
#define IX_ELEMS N_TOK                     // 16384

// Scratch (device globals — no allocation allowed)
__device__ float g_znorm[N_TOK];
__device__ float g_enorm[K_CODES];
__device__ int   g_idx[N_TOK];

// ---------------------------------------------------------------------------
// Kernel 1: row norms  znorm[n] = sum_c z[n,c]^2,  enorm[k] = sum_c e[k,c]^2
// ---------------------------------------------------------------------------
__global__ void norms_kernel(const float* __restrict__ z,
                             const float* __restrict__ emb) {
    int t = blockIdx.x * blockDim.x + threadIdx.x;
    if (t < N_TOK) {
        int b = t >> 10, hw = t & 1023;
        const float* p = z + (size_t)b * (CDIM * HWDIM) + hw;
        float s = 0.f;
        #pragma unroll 8
        for (int c = 0; c < CDIM; ++c) {
            float v = p[(size_t)c * HWDIM];
            s = __fmaf_rn(v, v, s);
        }
        g_znorm[t] = s;
    } else if (t < N_TOK + K_CODES) {
        int k = t - N_TOK;
        const float* p = emb + (size_t)k * CDIM;
        float s = 0.f;
        #pragma unroll 8
        for (int c = 0; c < CDIM; ++c) {
            float v = p[c];
            s = __fmaf_rn(v, v, s);
        }
        g_enorm[k] = s;
    }
}

// ---------------------------------------------------------------------------
// Kernel 2: argmin over codes.
// Block = 128 tokens, 256 threads (16x16), 8x8 register micro-tile.
// z tile [256 c][128 m] resident in smem; embedding streamed in 128-code
// chunks, 8 c-columns at a time, double buffered.
// ---------------------------------------------------------------------------
__global__ void __launch_bounds__(256, 1)
argmin_kernel(const float* __restrict__ z, const float* __restrict__ emb) {
    extern __shared__ float smem[];
    float (*As)[128] = (float (*)[128])smem;                       // [256][128]
    float (*Bs)[8][128] = (float (*)[8][128])(smem + CDIM * 128);  // [2][8][128]

    const int m0 = blockIdx.x * 128;
    const int b  = m0 >> 10;          // tile never straddles a batch image
    const int hw0 = m0 & 1023;
    const int tid = threadIdx.x;
    const int tx = tid & 15;
    const int ty = tid >> 4;

    // --- load z tile: As[c][m] = z[b, c, hw0+m] (coalesced float4) ---
    const float* zbase = z + (size_t)b * (CDIM * HWDIM) + hw0;
    #pragma unroll
    for (int i = 0; i < 32; ++i) {
        int v = tid + i * 256;            // 8192 float4 total
        int c = v >> 5, m4 = v & 31;
        float4 q4 = *(const float4*)(zbase + (size_t)c * HWDIM + m4 * 4);
        *(float4*)&As[c][m4 * 4] = q4;
    }

    float znr[8];
    #pragma unroll
    for (int i = 0; i < 8; ++i) znr[i] = g_znorm[m0 + ty * 8 + i];

    float best_d[8];
    int   best_i[8];
    #pragma unroll
    for (int i = 0; i < 8; ++i) { best_d[i] = CUDART_INF_F; best_i[i] = 0; }

    // --- prologue: stage iter 0 of embedding chunk ---
    const int kk = tid >> 1;          // code row within chunk (0..127)
    const int qq = tid & 1;           // which float4 of the 8-c slice
    float4 stage = *(const float4*)(emb + (size_t)kk * CDIM + qq * 4);
    Bs[0][qq * 4 + 0][kk] = stage.x;
    Bs[0][qq * 4 + 1][kk] = stage.y;
    Bs[0][qq * 4 + 2][kk] = stage.z;
    Bs[0][qq * 4 + 3][kk] = stage.w;
    __syncthreads();

    float acc[8][8];
    #pragma unroll
    for (int i = 0; i < 8; ++i)
        #pragma unroll
        for (int j = 0; j < 8; ++j) acc[i][j] = 0.f;

    int cur = 0;
    const int NITER = (K_CODES / 128) * (CDIM / 8);   // 64 * 32 = 2048

    for (int t = 0; t < NITER; ++t) {
        // prefetch next slice into registers (overlaps with compute)
        if (t + 1 < NITER) {
            int kc = (t + 1) >> 5;
            int c0 = ((t + 1) & 31) * 8;
            stage = *(const float4*)(emb + (size_t)(kc * 128 + kk) * CDIM + c0 + qq * 4);
        }

        const int cbase = (t & 31) * 8;
        #pragma unroll
        for (int cc = 0; cc < 8; ++cc) {
            float4 a0 = *(float4*)&As[cbase + cc][ty * 8];
            float4 a1 = *(float4*)&As[cbase + cc][ty * 8 + 4];
            float4 b0 = *(float4*)&Bs[cur][cc][tx * 8];
            float4 b1 = *(float4*)&Bs[cur][cc][tx * 8 + 4];
            float av[8] = {a0.x, a0.y, a0.z, a0.w, a1.x, a1.y, a1.z, a1.w};
            float bv[8] = {b0.x, b0.y, b0.z, b0.w, b1.x, b1.y, b1.z, b1.w};
            #pragma unroll
            for (int i = 0; i < 8; ++i)
                #pragma unroll
                for (int j = 0; j < 8; ++j)
                    acc[i][j] = __fmaf_rn(av[i], bv[j], acc[i][j]);
        }

        // end of a 128-code chunk: fold into running min (k ascending)
        if ((t & 31) == 31) {
            const int k0 = (t >> 5) * 128;
            float en[8];
            #pragma unroll
            for (int j = 0; j < 8; ++j) en[j] = g_enorm[k0 + tx * 8 + j];
            #pragma unroll
            for (int i = 0; i < 8; ++i) {
                #pragma unroll
                for (int j = 0; j < 8; ++j) {
                    // replicate reference rounding: fl(fl(zn+en) - fl(2*dot))
                    float s = __fadd_rn(znr[i], en[j]);
                    float d = __fsub_rn(s, __fmul_rn(2.0f, acc[i][j]));
                    if (d < best_d[i]) {          // strict <, k ascending => first-min
                        best_d[i] = d;
                        best_i[i] = k0 + tx * 8 + j;
                    }
                    acc[i][j] = 0.f;
                }
            }
        }

        // commit staged slice to the alternate buffer
        if (t + 1 < NITER) {
            Bs[cur ^ 1][qq * 4 + 0][kk] = stage.x;
            Bs[cur ^ 1][qq * 4 + 1][kk] = stage.y;
            Bs[cur ^ 1][qq * 4 + 2][kk] = stage.z;
            Bs[cur ^ 1][qq * 4 + 3][kk] = stage.w;
            __syncthreads();
            cur ^= 1;
        }
    }

    // --- cross-thread reduction over tx (16 partials per token) ---
    __syncthreads();
    float* red_d = smem;                 // [128][16]
    int*   red_i = (int*)(smem + 128 * 16);
    #pragma unroll
    for (int i = 0; i < 8; ++i) {
        red_d[(ty * 8 + i) * 16 + tx] = best_d[i];
        red_i[(ty * 8 + i) * 16 + tx] = best_i[i];
    }
    __syncthreads();
    if (tid < 128) {
        float bd = red_d[tid * 16];
        int   bi = red_i[tid * 16];
        #pragma unroll
        for (int x = 1; x < 16; ++x) {
            float d = red_d[tid * 16 + x];
            int   ii = red_i[tid * 16 + x];
            if (d < bd || (d == bd && ii < bi)) { bd = d; bi = ii; }
        }
        g_idx[m0 + tid] = bi;
    }
}

// ---------------------------------------------------------------------------
// Kernel 3: outputs.  One block per token, 256 threads = channel.
//  z_q (BCHW, straight-through fl(z + fl(e-z))), loss (BHWC, fl(0.25*d2+d2)),
//  idx as float. Offsets < 0 mean "don't write".
// ---------------------------------------------------------------------------
__global__ void output_kernel(const float* __restrict__ z,
                              const float* __restrict__ emb,
                              float* __restrict__ out,
                              int zq_off, int loss_off, int idx_off) {
    int n = blockIdx.x;
    int c = threadIdx.x;
    int b = n >> 10, hw = n & 1023;
    int idx = g_idx[n];

    float e  = emb[(size_t)idx * CDIM + c];
    float zv = z[(size_t)b * (CDIM * HWDIM) + (size_t)c * HWDIM + hw];

    float dq = __fsub_rn(e, zv);                 // z_q - z (stop-grad equal)
    float zq = __fadd_rn(zv, dq);                // straight-through estimator
    float d2 = __fmul_rn(dq, dq);
    float loss = __fadd_rn(__fmul_rn(0.25f, d2), d2);

    if (zq_off >= 0)
        out[(size_t)zq_off + (size_t)b * (CDIM * HWDIM) + (size_t)c * HWDIM + hw] = zq;
    if (loss_off >= 0)
        out[(size_t)loss_off + (size_t)n * CDIM + c] = loss;
    if (idx_off >= 0 && c == 0)
        out[(size_t)idx_off + n] = (float)idx;
}

// ---------------------------------------------------------------------------
extern "C" void kernel_launch(void* const* d_in, const int* in_sizes, int n_in,
                              void* d_out, int out_size) {
    // Defensive input identification by size: z has 4194304 elems, emb 2097152.
    const float* z   = (const float*)d_in[0];
    const float* emb = (const float*)d_in[1];
    if (n_in >= 2 && in_sizes[0] == K_CODES * CDIM && in_sizes[1] == ZQ_ELEMS) {
        z   = (const float*)d_in[1];
        emb = (const float*)d_in[0];
    }
    float* out = (float*)d_out;

    norms_kernel<<<(N_TOK + K_CODES + 255) / 256, 256>>>(z, emb);

    const int smem_bytes = (CDIM * 128 + 2 * 8 * 128) * (int)sizeof(float); // 139264
    cudaFuncSetAttribute(argmin_kernel,
                         cudaFuncAttributeMaxDynamicSharedMemorySize, smem_bytes);
    argmin_kernel<<<N_TOK / 128, 256, smem_bytes>>>(z, emb);

    // Decide output layout from out_size at runtime (metadata not visible here).
    int zq_off = -1, loss_off = -1, idx_off = -1;
    if (out_size == 2 * ZQ_ELEMS + IX_ELEMS) {        // [z_q | loss | idx]
        zq_off = 0; loss_off = ZQ_ELEMS; idx_off = 2 * ZQ_ELEMS;
    } else if (out_size == 2 * ZQ_ELEMS) {            // [z_q | loss]
        zq_off = 0; loss_off = ZQ_ELEMS;
    } else if (out_size == ZQ_ELEMS + IX_ELEMS) {     // [z_q | idx]
        zq_off = 0; idx_off = ZQ_ELEMS;
    } else if (out_size == ZQ_ELEMS) {                // [z_q]
        zq_off = 0;
    } else if (out_size == IX_ELEMS) {                // [idx]
        idx_off = 0;
    } else {                                           // best effort, fill in order
        int rem = out_size;
        if (rem >= ZQ_ELEMS) { zq_off = 0; rem -= ZQ_ELEMS; }
        if (rem >= ZQ_ELEMS) { loss_off = ZQ_ELEMS; rem -= ZQ_ELEMS; }
        if (rem >= IX_ELEMS) { idx_off = out_size - IX_ELEMS; }
    }

    output_kernel<<<N_TOK, 256>>>(z, emb, out, zq_off, loss_off, idx_off);
}

// round 4
// speedup vs baseline: 1.9111x; 1.9111x over previous
#include <cuda_runtime.h>
#include <cuda_bf16.h>
#include <math_constants.h>
#include <cstdint>

#define BATCH 16
#define CDIM 256
#define HWDIM 1024
#define N_TOK 16384
#define K_CODES 8192
#define ZQ_ELEMS (BATCH*CDIM*HWDIM)
#define IX_ELEMS N_TOK

#define TILE_M 128
#define CHUNK_N 64
#define NCHUNK (K_CODES/CHUNK_N)     // 128
#define CAP 96
#define MARGIN 1e-3f

// smem byte offsets (dynamic smem)
#define OFF_AS 0                      // bf16 [128][264] = 67584
#define OFF_BS 67584                  // bf16 2 x [64][264] = 67584
#define BS_BUF 33792
#define OFF_MIN 135168                // uint [128]
#define OFF_CNT 135680                // int  [128]
#define OFF_CAND 136192               // int  [128][96]
#define SMEM_TOTAL 185344
#define ROWB 528                      // padded row stride in bytes (264 bf16)

__device__ __align__(16) __nv_bfloat16 g_embf[K_CODES*CDIM];   // 4MB scratch
__device__ float g_enorm[K_CODES];
__device__ int g_idx[N_TOK];

__device__ __forceinline__ uint32_t smem_u32(const void* p){
    uint32_t a;
    asm("{ .reg .u64 t; cvta.to.shared.u64 t, %1; cvt.u32.u64 %0, t; }":"=r"(a):"l"(p));
    return a;
}
__device__ __forceinline__ unsigned fkey(float f){
    unsigned b = __float_as_uint(f);
    return (b & 0x80000000u) ? ~b : (b | 0x80000000u);
}
__device__ __forceinline__ float funkey(unsigned u){
    return __uint_as_float((u & 0x80000000u) ? (u ^ 0x80000000u) : ~u);
}
#define LDM_X4(r0,r1,r2,r3,addr) \
    asm volatile("ldmatrix.sync.aligned.m8n8.x4.shared.b16 {%0,%1,%2,%3}, [%4];" \
        :"=r"(r0),"=r"(r1),"=r"(r2),"=r"(r3):"r"(addr))
#define MMA_BF16(c0,c1,c2,c3,a0,a1,a2,a3,b0,b1) \
    asm volatile("mma.sync.aligned.m16n8k16.row.col.f32.bf16.bf16.f32 " \
        "{%0,%1,%2,%3},{%4,%5,%6,%7},{%8,%9},{%0,%1,%2,%3};" \
        :"+f"(c0),"+f"(c1),"+f"(c2),"+f"(c3) \
        :"r"(a0),"r"(a1),"r"(a2),"r"(a3),"r"(b0),"r"(b1))
#define CP_ASYNC16(dst,src) \
    asm volatile("cp.async.cg.shared.global [%0], [%1], 16;"::"r"(dst),"l"(src))
#define CP_COMMIT() asm volatile("cp.async.commit_group;":::"memory")
#define CP_WAIT1() asm volatile("cp.async.wait_group 1;":::"memory")

// ---------- enorm: exact serial-ascending FMA (round-1-verified rounding) ----------
__global__ void enorm_kernel(const float* __restrict__ emb){
    int k = blockIdx.x*blockDim.x + threadIdx.x;
    if(k >= K_CODES) return;
    const float* p = emb + (size_t)k*CDIM;
    float s = 0.f;
    #pragma unroll 16
    for(int c=0;c<CDIM;++c) s = __fmaf_rn(p[c], p[c], s);
    g_enorm[k] = s;
}

// ---------- codebook fp32 -> bf16 ----------
__global__ void cvt_kernel(const float* __restrict__ emb){
    int i = blockIdx.x*blockDim.x + threadIdx.x;   // < 2M/4
    float4 v = ((const float4*)emb)[i];
    __nv_bfloat162 lo = __floats2bfloat162_rn(v.x, v.y);
    __nv_bfloat162 hi = __floats2bfloat162_rn(v.z, v.w);
    ((__nv_bfloat162*)g_embf)[i*2]   = lo;
    ((__nv_bfloat162*)g_embf)[i*2+1] = hi;
}

// ---------- main: bf16 mma.sync distance GEMM + margin candidates + exact rescore ----------
__global__ void __launch_bounds__(256,1)
vq_main(const float* __restrict__ z, const float* __restrict__ emb){
    extern __shared__ char smem[];
    const uint32_t sb = smem_u32(smem);
    const int tid = threadIdx.x;
    const int lane = tid & 31, warp = tid >> 5;
    const int wm = warp & 3, wn = warp >> 2;       // warp tile: (wm*32 m) x (wn*32 n)
    const int g = lane >> 2, t4 = lane & 3;
    const int m0 = blockIdx.x*TILE_M;
    const int b = m0 >> 10, hw0 = m0 & 1023;

    unsigned* s_min = (unsigned*)(smem + OFF_MIN);
    int* s_cnt = (int*)(smem + OFF_CNT);
    int* s_cand = (int*)(smem + OFF_CAND);
    if(tid < 128){ s_min[tid] = 0xFFFFFFFFu; s_cnt[tid] = 0; }

    // ---- z tile -> bf16 As[m][c], row stride 264 bf16 ----
    const float* zb = z + (size_t)b*(CDIM*HWDIM) + hw0;
    #pragma unroll
    for(int i=0;i<32;++i){
        int v = tid + i*256;
        int c = v >> 5, m4 = (v & 31)*4;
        float4 q = *(const float4*)(zb + (size_t)c*HWDIM + m4);
        *(__nv_bfloat16*)(smem + (m4+0)*ROWB + c*2) = __float2bfloat16_rn(q.x);
        *(__nv_bfloat16*)(smem + (m4+1)*ROWB + c*2) = __float2bfloat16_rn(q.y);
        *(__nv_bfloat16*)(smem + (m4+2)*ROWB + c*2) = __float2bfloat16_rn(q.z);
        *(__nv_bfloat16*)(smem + (m4+3)*ROWB + c*2) = __float2bfloat16_rn(q.w);
    }

    // ldmatrix lane base addresses
    uint32_t a_base[2], b_base[2];
    #pragma unroll
    for(int mt=0;mt<2;++mt)
        a_base[mt] = sb + (uint32_t)((wm*32 + mt*16 + (lane & 15))*ROWB
                                     + ((lane >> 4) & 1)*16);
    #pragma unroll
    for(int nh=0;nh<2;++nh)
        b_base[nh] = sb + OFF_BS + (uint32_t)((wn*32 + nh*16 + ((lane >> 4) & 1)*8
                                     + (lane & 7))*ROWB + ((lane >> 3) & 1)*16);

    // ---- prefetch chunk 0 ----
    {
        const __nv_bfloat16* src = g_embf;
        #pragma unroll
        for(int i=0;i<8;++i){
            int seg = tid + i*256;                 // 2048 segs of 16B
            int n = seg >> 5, c16 = seg & 31;
            CP_ASYNC16(sb + OFF_BS + (uint32_t)(n*ROWB + c16*16), src + n*CDIM + c16*8);
        }
        CP_COMMIT();
    }
    __syncthreads();

    for(int ch=0; ch<NCHUNK; ++ch){
        const int buf = ch & 1;
        const int k0 = ch*CHUNK_N;
        if(ch+1 < NCHUNK){
            const __nv_bfloat16* src = g_embf + (size_t)(ch+1)*CHUNK_N*CDIM;
            const uint32_t bdst = sb + OFF_BS + (uint32_t)((buf^1)*BS_BUF);
            #pragma unroll
            for(int i=0;i<8;++i){
                int seg = tid + i*256;
                int n = seg >> 5, c16 = seg & 31;
                CP_ASYNC16(bdst + (uint32_t)(n*ROWB + c16*16), src + n*CDIM + c16*8);
            }
        }
        CP_COMMIT();
        CP_WAIT1();
        __syncthreads();

        // ---- GEMM: 32m x 32n per warp, K=256 ----
        float acc[2][4][4];
        #pragma unroll
        for(int mt=0;mt<2;++mt)
            #pragma unroll
            for(int nt=0;nt<4;++nt)
                #pragma unroll
                for(int r=0;r<4;++r) acc[mt][nt][r] = 0.f;

        const uint32_t boff = (uint32_t)(buf*BS_BUF);
        #pragma unroll 4
        for(int ks=0; ks<16; ++ks){
            const uint32_t koff = ks*32;
            uint32_t a[2][4], bf[2][4];
            LDM_X4(a[0][0],a[0][1],a[0][2],a[0][3], a_base[0] + koff);
            LDM_X4(a[1][0],a[1][1],a[1][2],a[1][3], a_base[1] + koff);
            LDM_X4(bf[0][0],bf[0][1],bf[0][2],bf[0][3], b_base[0] + boff + koff);
            LDM_X4(bf[1][0],bf[1][1],bf[1][2],bf[1][3], b_base[1] + boff + koff);
            #pragma unroll
            for(int mt=0;mt<2;++mt)
                #pragma unroll
                for(int nt=0;nt<4;++nt)
                    MMA_BF16(acc[mt][nt][0],acc[mt][nt][1],acc[mt][nt][2],acc[mt][nt][3],
                             a[mt][0],a[mt][1],a[mt][2],a[mt][3],
                             bf[nt>>1][(nt&1)*2], bf[nt>>1][(nt&1)*2+1]);
        }

        // ---- epilogue phase a: d = enorm - 2*acc, atomicMin per token ----
        #pragma unroll
        for(int mt=0;mt<2;++mt){
            float dmin[2] = {CUDART_INF_F, CUDART_INF_F};
            #pragma unroll
            for(int nt=0;nt<4;++nt){
                int nb = k0 + wn*32 + nt*8 + 2*t4;
                float en0 = __ldg(&g_enorm[nb]);
                float en1 = __ldg(&g_enorm[nb+1]);
                #pragma unroll
                for(int r=0;r<4;++r){
                    float d = __fmaf_rn(-2.f, acc[mt][nt][r], (r&1) ? en1 : en0);
                    acc[mt][nt][r] = d;
                    if(d < dmin[r>>1]) dmin[r>>1] = d;
                }
            }
            #pragma unroll
            for(int h=0;h<2;++h)
                atomicMin(&s_min[wm*32 + mt*16 + g + h*8], fkey(dmin[h]));
        }
        __syncthreads();

        // ---- phase b: push candidates within margin of running min ----
        #pragma unroll
        for(int mt=0;mt<2;++mt){
            #pragma unroll
            for(int h=0;h<2;++h){
                int m = wm*32 + mt*16 + g + h*8;
                float thr = funkey(s_min[m]) + MARGIN;
                #pragma unroll
                for(int nt=0;nt<4;++nt){
                    #pragma unroll
                    for(int q=0;q<2;++q){
                        float d = acc[mt][nt][h*2+q];
                        if(d <= thr){
                            int slot = atomicAdd(&s_cnt[m], 1);
                            if(slot < CAP) s_cand[m*CAP + slot] = k0 + wn*32 + nt*8 + 2*t4 + q;
                        }
                    }
                }
            }
        }
        __syncthreads();
    }

    // ---- reload exact fp32 z tile into freed A/B smem (stride 257 floats) ----
    float* zf = (float*)smem;
    #pragma unroll
    for(int i=0;i<32;++i){
        int v = tid + i*256;
        int c = v >> 5, m4 = (v & 31)*4;
        float4 q = *(const float4*)(zb + (size_t)c*HWDIM + m4);
        zf[(m4+0)*257 + c] = q.x;
        zf[(m4+1)*257 + c] = q.y;
        zf[(m4+2)*257 + c] = q.z;
        zf[(m4+3)*257 + c] = q.w;
    }
    __syncthreads();

    // ---- exact fp32 rescore (serial-FMA rounding == reference path) ----
    if(tid < 128){
        float zn = 0.f;
        #pragma unroll 8
        for(int c=0;c<CDIM;++c){
            float v = zf[tid*257 + c];
            zn = __fmaf_rn(v, v, zn);
        }
        int cn = s_cnt[tid]; if(cn > CAP) cn = CAP;
        float best = CUDART_INF_F; int bi = 0x7FFFFFFF;
        for(int i=0;i<cn;++i){
            int k = s_cand[tid*CAP + i];
            const float* er = emb + (size_t)k*CDIM;
            float acc = 0.f;
            #pragma unroll 8
            for(int c=0;c<CDIM;++c)
                acc = __fmaf_rn(zf[tid*257 + c], er[c], acc);
            float dd = __fsub_rn(__fadd_rn(zn, g_enorm[k]), __fmul_rn(2.f, acc));
            if(dd < best || (dd == best && k < bi)){ best = dd; bi = k; }
        }
        g_idx[m0 + tid] = bi;
    }
}

// ---------- outputs ----------
__global__ void output_kernel(const float* __restrict__ z, const float* __restrict__ emb,
                              float* __restrict__ out, int zq_off, int loss_off, int idx_off){
    int n = blockIdx.x, c = threadIdx.x;
    int b = n >> 10, hw = n & 1023;
    int idx = g_idx[n];
    float e  = emb[(size_t)idx*CDIM + c];
    float zv = z[(size_t)b*(CDIM*HWDIM) + (size_t)c*HWDIM + hw];
    float dq = __fsub_rn(e, zv);
    float zq = __fadd_rn(zv, dq);
    float d2 = __fmul_rn(dq, dq);
    float loss = __fadd_rn(__fmul_rn(0.25f, d2), d2);
    if(zq_off  >= 0) out[(size_t)zq_off + (size_t)b*(CDIM*HWDIM) + (size_t)c*HWDIM + hw] = zq;
    if(loss_off>= 0) out[(size_t)loss_off + (size_t)n*CDIM + c] = loss;
    if(idx_off >= 0 && c == 0) out[(size_t)idx_off + n] = (float)idx;
}

extern "C" void kernel_launch(void* const* d_in, const int* in_sizes, int n_in,
                              void* d_out, int out_size){
    const float* z   = (const float*)d_in[0];
    const float* emb = (const float*)d_in[1];
    if(n_in >= 2 && in_sizes[0] == K_CODES*CDIM && in_sizes[1] == ZQ_ELEMS){
        z = (const float*)d_in[1]; emb = (const float*)d_in[0];
    }
    float* out = (float*)d_out;

    enorm_kernel<<<K_CODES/256, 256>>>(emb);
    cvt_kernel<<<(K_CODES*CDIM/4)/256, 256>>>(emb);

    cudaFuncSetAttribute(vq_main, cudaFuncAttributeMaxDynamicSharedMemorySize, SMEM_TOTAL);
    vq_main<<<N_TOK/TILE_M, 256, SMEM_TOTAL>>>(z, emb);

    int zq_off=-1, loss_off=-1, idx_off=-1;
    if(out_size == 2*ZQ_ELEMS + IX_ELEMS){ zq_off=0; loss_off=ZQ_ELEMS; idx_off=2*ZQ_ELEMS; }
    else if(out_size == 2*ZQ_ELEMS){ zq_off=0; loss_off=ZQ_ELEMS; }
    else if(out_size == ZQ_ELEMS + IX_ELEMS){ zq_off=0; idx_off=ZQ_ELEMS; }
    else if(out_size == ZQ_ELEMS){ zq_off=0; }
    else if(out_size == IX_ELEMS){ idx_off=0; }
    else{
        int rem = out_size;
        if(rem >= ZQ_ELEMS){ zq_off=0; rem -= ZQ_ELEMS; }
        if(rem >= ZQ_ELEMS){ loss_off=ZQ_ELEMS; rem -= ZQ_ELEMS; }
        if(rem >= IX_ELEMS){ idx_off = out_size - IX_ELEMS; }
    }
    output_kernel<<<N_TOK, 256>>>(z, emb, out, zq_off, loss_off, idx_off);
}

// round 7
// speedup vs baseline: 2.1260x; 1.1125x over previous
#include <cuda_runtime.h>
#include <cuda_bf16.h>
#include <math_constants.h>
#include <cstdint>

#define BATCH 16
#define CDIM 256
#define HWDIM 1024
#define N_TOK 16384
#define K_CODES 8192
#define ZQ_ELEMS (BATCH*CDIM*HWDIM)
#define IX_ELEMS N_TOK

#define TILE_M 128
#define CHUNK_N 128
#define NCHUNK 64
#define CAP 96
#define MARGIN 1e-3f
#define ROWB 528                     // padded row stride bytes (264 bf16)

// smem byte offsets
#define OFF_BS 67584                 // A: [0,67584) = 128 x 528
#define BS_BUF 67584                 // B: 2 x (128 x 528)
#define OFF_CAND 202752              // uint16 [128][96] = 24576
#define OFF_CNT 227328               // int [128]
#define OFF_SMIN 227840              // uint [128]
#define SMEM_TOTAL 228352

__device__ __align__(16) __nv_bfloat16 g_embf[K_CODES*CDIM];
__device__ float g_enorm[K_CODES];
__device__ int g_idx[N_TOK];

__device__ __forceinline__ uint32_t smem_u32(const void* p){
    uint32_t a;
    asm("{ .reg .u64 t; cvta.to.shared.u64 t, %1; cvt.u32.u64 %0, t; }":"=r"(a):"l"(p));
    return a;
}
__device__ __forceinline__ unsigned fkey(float f){
    unsigned b = __float_as_uint(f);
    return (b & 0x80000000u) ? ~b : (b | 0x80000000u);
}
__device__ __forceinline__ float funkey(unsigned u){
    return __uint_as_float((u & 0x80000000u) ? (u ^ 0x80000000u) : ~u);
}
#define LDM_X4(r0,r1,r2,r3,addr) \
    asm volatile("ldmatrix.sync.aligned.m8n8.x4.shared.b16 {%0,%1,%2,%3}, [%4];" \
        :"=r"(r0),"=r"(r1),"=r"(r2),"=r"(r3):"r"(addr))
#define MMA_BF16(c0,c1,c2,c3,a0,a1,a2,a3,b0,b1) \
    asm volatile("mma.sync.aligned.m16n8k16.row.col.f32.bf16.bf16.f32 " \
        "{%0,%1,%2,%3},{%4,%5,%6,%7},{%8,%9},{%0,%1,%2,%3};" \
        :"+f"(c0),"+f"(c1),"+f"(c2),"+f"(c3) \
        :"r"(a0),"r"(a1),"r"(a2),"r"(a3),"r"(b0),"r"(b1))
#define CP_ASYNC16(dst,src) \
    asm volatile("cp.async.cg.shared.global [%0], [%1], 16;"::"r"(dst),"l"(src))
#define CP_COMMIT() asm volatile("cp.async.commit_group;":::"memory")
#define CP_WAIT1() asm volatile("cp.async.wait_group 1;":::"memory")

// ---------- prologue: enorm (serial-ascending FMA, verified rounding) + bf16 cvt ----------
__global__ void prep_kernel(const float* __restrict__ emb){
    int k = blockIdx.x*blockDim.x + threadIdx.x;
    const float4* p = (const float4*)(emb + (size_t)k*CDIM);
    __nv_bfloat162* q = (__nv_bfloat162*)(g_embf + (size_t)k*CDIM);
    float s = 0.f;
    #pragma unroll 8
    for(int i=0;i<64;++i){
        float4 v = p[i];
        s=__fmaf_rn(v.x,v.x,s); s=__fmaf_rn(v.y,v.y,s);
        s=__fmaf_rn(v.z,v.z,s); s=__fmaf_rn(v.w,v.w,s);
        q[i*2]   = __floats2bfloat162_rn(v.x, v.y);
        q[i*2+1] = __floats2bfloat162_rn(v.z, v.w);
    }
    g_enorm[k] = s;
}

// ---------- main: HMMA distance GEMM + margin candidates + exact rescore ----------
__global__ void __launch_bounds__(256,1)
vq_main(const float* __restrict__ z, const float* __restrict__ emb){
    extern __shared__ char smem[];
    const uint32_t sb = smem_u32(smem);
    const int tid = threadIdx.x;
    const int lane = tid & 31, warp = tid >> 5;
    const int wm = warp & 3, wn = warp >> 2;      // 8 warps: 32m x 64n each
    const int g = lane >> 2, t4 = lane & 3;
    const int m0 = blockIdx.x*TILE_M;
    const int b = m0 >> 10, hw0 = m0 & 1023;

    unsigned* s_min = (unsigned*)(smem + OFF_SMIN);
    int* s_cnt = (int*)(smem + OFF_CNT);
    unsigned short* s_cand = (unsigned short*)(smem + OFF_CAND);
    if(tid < 128){ s_min[tid] = 0xFFFFFFFFu; s_cnt[tid] = 0; }

    // ---- z tile -> bf16 A (round-4 layout) ----
    const float* zb = z + (size_t)b*(CDIM*HWDIM) + hw0;
    #pragma unroll
    for(int i=0;i<32;++i){
        int v = tid + i*256;
        int c = v >> 5, m4 = (v & 31)*4;
        float4 q = *(const float4*)(zb + (size_t)c*HWDIM + m4);
        *(__nv_bfloat16*)(smem + (m4+0)*ROWB + c*2) = __float2bfloat16_rn(q.x);
        *(__nv_bfloat16*)(smem + (m4+1)*ROWB + c*2) = __float2bfloat16_rn(q.y);
        *(__nv_bfloat16*)(smem + (m4+2)*ROWB + c*2) = __float2bfloat16_rn(q.z);
        *(__nv_bfloat16*)(smem + (m4+3)*ROWB + c*2) = __float2bfloat16_rn(q.w);
    }

    // ---- stage chunk 0 ----
    {
        const __nv_bfloat16* src = g_embf;
        #pragma unroll
        for(int i=0;i<16;++i){
            int seg = tid + i*256;                 // 4096 segs of 16B
            int n = seg >> 5, c16 = seg & 31;
            CP_ASYNC16(sb + OFF_BS + (uint32_t)(n*ROWB + c16*16),
                       src + (size_t)n*CDIM + c16*8);
        }
        CP_COMMIT();
    }

    // ldmatrix lane base addresses
    uint32_t a_base[2], b_base[4];
    #pragma unroll
    for(int mt=0;mt<2;++mt)
        a_base[mt] = sb + (uint32_t)((wm*32 + mt*16 + (lane & 15))*ROWB
                                     + ((lane >> 4) & 1)*16);
    #pragma unroll
    for(int nh=0;nh<4;++nh)
        b_base[nh] = sb + OFF_BS + (uint32_t)((wn*64 + nh*16 + ((lane >> 4) & 1)*8
                                     + (lane & 7))*ROWB + ((lane >> 3) & 1)*16);

    float rmv[2][2] = {{CUDART_INF_F, CUDART_INF_F},{CUDART_INF_F, CUDART_INF_F}};

    for(int ch=0; ch<NCHUNK; ++ch){
        const int buf = ch & 1;
        const int k0 = ch*CHUNK_N;
        if(ch+1 < NCHUNK){
            const __nv_bfloat16* src = g_embf + (size_t)(ch+1)*CHUNK_N*CDIM;
            const uint32_t bdst = sb + OFF_BS + (uint32_t)((buf^1)*BS_BUF);
            #pragma unroll
            for(int i=0;i<16;++i){
                int seg = tid + i*256;
                int n = seg >> 5, c16 = seg & 31;
                CP_ASYNC16(bdst + (uint32_t)(n*ROWB + c16*16),
                           src + (size_t)n*CDIM + c16*8);
            }
        }
        CP_COMMIT();
        CP_WAIT1();
        __syncthreads();

        // ---- GEMM: 32m x 64n per warp, K=256 ----
        float acc[2][8][4];
        #pragma unroll
        for(int mt=0;mt<2;++mt)
            #pragma unroll
            for(int nt=0;nt<8;++nt)
                #pragma unroll
                for(int r=0;r<4;++r) acc[mt][nt][r] = 0.f;

        const uint32_t boff = (uint32_t)(buf*BS_BUF);
        #pragma unroll 4
        for(int ks=0; ks<16; ++ks){
            const uint32_t koff = (uint32_t)(ks*32);
            uint32_t a[2][4], bq[4][4];
            LDM_X4(a[0][0],a[0][1],a[0][2],a[0][3], a_base[0] + koff);
            LDM_X4(a[1][0],a[1][1],a[1][2],a[1][3], a_base[1] + koff);
            LDM_X4(bq[0][0],bq[0][1],bq[0][2],bq[0][3], b_base[0] + boff + koff);
            LDM_X4(bq[1][0],bq[1][1],bq[1][2],bq[1][3], b_base[1] + boff + koff);
            LDM_X4(bq[2][0],bq[2][1],bq[2][2],bq[2][3], b_base[2] + boff + koff);
            LDM_X4(bq[3][0],bq[3][1],bq[3][2],bq[3][3], b_base[3] + boff + koff);
            #pragma unroll
            for(int mt=0;mt<2;++mt)
                #pragma unroll
                for(int nt=0;nt<8;++nt)
                    MMA_BF16(acc[mt][nt][0],acc[mt][nt][1],acc[mt][nt][2],acc[mt][nt][3],
                             a[mt][0],a[mt][1],a[mt][2],a[mt][3],
                             bq[nt>>1][(nt&1)*2], bq[nt>>1][(nt&1)*2+1]);
        }

        // ---- phase a: d = enorm - 2*acc (in place), chunk min, record-improve atomic ----
        float en0[8], en1[8];
        #pragma unroll
        for(int nt=0;nt<8;++nt){
            int nb = k0 + wn*64 + nt*8 + 2*t4;
            en0[nt] = __ldg(&g_enorm[nb]); en1[nt] = __ldg(&g_enorm[nb+1]);
        }
        float cmin[2][2];
        #pragma unroll
        for(int mt=0;mt<2;++mt)
            #pragma unroll
            for(int h=0;h<2;++h){
                float cm = CUDART_INF_F;
                #pragma unroll
                for(int nt=0;nt<8;++nt){
                    float d0 = __fmaf_rn(-2.f, acc[mt][nt][2*h],   en0[nt]);
                    float d1 = __fmaf_rn(-2.f, acc[mt][nt][2*h+1], en1[nt]);
                    acc[mt][nt][2*h] = d0; acc[mt][nt][2*h+1] = d1;
                    if(d0 < cm) cm = d0;
                    if(d1 < cm) cm = d1;
                }
                cmin[mt][h] = cm;
                if(cm < rmv[mt][h]){
                    rmv[mt][h] = cm;
                    atomicMin(&s_min[wm*32 + mt*16 + g + h*8], fkey(cm));
                }
            }
        __syncthreads();

        // ---- phase b: push candidates within margin (skip if chunk can't qualify) ----
        #pragma unroll
        for(int mt=0;mt<2;++mt)
            #pragma unroll
            for(int h=0;h<2;++h){
                int m = wm*32 + mt*16 + g + h*8;
                float thr = funkey(s_min[m]) + MARGIN;
                if(cmin[mt][h] <= thr){
                    #pragma unroll
                    for(int nt=0;nt<8;++nt){
                        #pragma unroll
                        for(int q=0;q<2;++q){
                            float d = acc[mt][nt][2*h+q];
                            if(d <= thr){
                                int slot = atomicAdd(&s_cnt[m], 1);
                                if(slot < CAP)
                                    s_cand[m*CAP + slot] =
                                        (unsigned short)(k0 + wn*64 + nt*8 + 2*t4 + q);
                            }
                        }
                    }
                }
            }
    }
    __syncthreads();

    // ---- reload exact fp32 z tile into freed A/B smem ----
    float* zf = (float*)smem;
    #pragma unroll
    for(int i=0;i<32;++i){
        int v = tid + i*256;
        int c = v >> 5, m4 = (v & 31)*4;
        float4 q = *(const float4*)(zb + (size_t)c*HWDIM + m4);
        zf[(m4+0)*257 + c] = q.x; zf[(m4+1)*257 + c] = q.y;
        zf[(m4+2)*257 + c] = q.z; zf[(m4+3)*257 + c] = q.w;
    }
    __syncthreads();

    // ---- exact fp32 rescore (serial-FMA rounding == reference path) ----
    if(tid < 128){
        float zn = 0.f;
        #pragma unroll 8
        for(int c=0;c<CDIM;++c){
            float v = zf[tid*257 + c];
            zn = __fmaf_rn(v, v, zn);
        }
        int cn = s_cnt[tid]; if(cn > CAP) cn = CAP;
        float best = CUDART_INF_F; int bi = 0x7FFFFFFF;
        for(int i=0;i<cn;++i){
            int k = (int)s_cand[tid*CAP + i];
            const float* er = emb + (size_t)k*CDIM;
            float acc2 = 0.f;
            #pragma unroll 8
            for(int c=0;c<CDIM;++c)
                acc2 = __fmaf_rn(zf[tid*257 + c], er[c], acc2);
            float dd = __fsub_rn(__fadd_rn(zn, g_enorm[k]), __fmul_rn(2.f, acc2));
            if(dd < best || (dd == best && k < bi)){ best = dd; bi = k; }
        }
        g_idx[m0 + tid] = bi;
    }
}

// ---------- outputs (passing since round 1) ----------
__global__ void output_kernel(const float* __restrict__ z, const float* __restrict__ emb,
                              float* __restrict__ out, int zq_off, int loss_off, int idx_off){
    int n = blockIdx.x, c = threadIdx.x;
    int b = n >> 10, hw = n & 1023;
    int idx = g_idx[n];
    float e  = emb[(size_t)idx*CDIM + c];
    float zv = z[(size_t)b*(CDIM*HWDIM) + (size_t)c*HWDIM + hw];
    float dq = __fsub_rn(e, zv);
    float zq = __fadd_rn(zv, dq);
    float d2 = __fmul_rn(dq, dq);
    float loss = __fadd_rn(__fmul_rn(0.25f, d2), d2);
    if(zq_off  >= 0) out[(size_t)zq_off + (size_t)b*(CDIM*HWDIM) + (size_t)c*HWDIM + hw] = zq;
    if(loss_off>= 0) out[(size_t)loss_off + (size_t)n*CDIM + c] = loss;
    if(idx_off >= 0 && c == 0) out[(size_t)idx_off + n] = (float)idx;
}

extern "C" void kernel_launch(void* const* d_in, const int* in_sizes, int n_in,
                              void* d_out, int out_size){
    const float* z   = (const float*)d_in[0];
    const float* emb = (const float*)d_in[1];
    if(n_in >= 2 && in_sizes[0] == K_CODES*CDIM && in_sizes[1] == ZQ_ELEMS){
        z = (const float*)d_in[1]; emb = (const float*)d_in[0];
    }
    float* out = (float*)d_out;

    prep_kernel<<<K_CODES/256, 256>>>(emb);

    cudaFuncSetAttribute(vq_main, cudaFuncAttributeMaxDynamicSharedMemorySize, SMEM_TOTAL);
    vq_main<<<N_TOK/TILE_M, 256, SMEM_TOTAL>>>(z, emb);

    int zq_off=-1, loss_off=-1, idx_off=-1;
    if(out_size == 2*ZQ_ELEMS + IX_ELEMS){ zq_off=0; loss_off=ZQ_ELEMS; idx_off=2*ZQ_ELEMS; }
    else if(out_size == 2*ZQ_ELEMS){ zq_off=0; loss_off=ZQ_ELEMS; }
    else if(out_size == ZQ_ELEMS + IX_ELEMS){ zq_off=0; idx_off=ZQ_ELEMS; }
    else if(out_size == ZQ_ELEMS){ zq_off=0; }
    else if(out_size == IX_ELEMS){ idx_off=0; }
    else{
        int rem = out_size;
        if(rem >= ZQ_ELEMS){ zq_off=0; rem -= ZQ_ELEMS; }
        if(rem >= ZQ_ELEMS){ loss_off=ZQ_ELEMS; rem -= ZQ_ELEMS; }
        if(rem >= IX_ELEMS){ idx_off = out_size - IX_ELEMS; }
    }
    output_kernel<<<N_TOK, 256>>>(z, emb, out, zq_off, loss_off, idx_off);
}

// round 8
// speedup vs baseline: 2.2019x; 1.0357x over previous
#include <cuda_runtime.h>
#include <cuda_bf16.h>
#include <math_constants.h>
#include <cstdint>

#define BATCH 16
#define CDIM 256
#define HWDIM 1024
#define N_TOK 16384
#define K_CODES 8192
#define ZQ_ELEMS (BATCH*CDIM*HWDIM)
#define IX_ELEMS N_TOK

#define TILE_M 128
#define CHUNK_N 128
#define NCHUNK 64
#define CAP 96
#define MARGIN 1e-3f
#define ROWB 528                     // padded row stride bytes (264 bf16)
#define NTHREADS 512

// smem byte offsets
#define OFF_BS 67584                 // A: [0,67584) = 128 x 528
#define BS_BUF 67584                 // B: 2 x (128 x 528)
#define OFF_CAND 202752              // uint16 [128][96] = 24576
#define OFF_CNT 227328               // int [128]
#define OFF_SMIN 227840              // uint [128]
#define SMEM_TOTAL 228352

__device__ __align__(16) __nv_bfloat16 g_embf[K_CODES*CDIM];
__device__ float g_enorm[K_CODES];
__device__ int g_idx[N_TOK];

__device__ __forceinline__ uint32_t smem_u32(const void* p){
    uint32_t a;
    asm("{ .reg .u64 t; cvta.to.shared.u64 t, %1; cvt.u32.u64 %0, t; }":"=r"(a):"l"(p));
    return a;
}
__device__ __forceinline__ unsigned fkey(float f){
    unsigned b = __float_as_uint(f);
    return (b & 0x80000000u) ? ~b : (b | 0x80000000u);
}
__device__ __forceinline__ float funkey(unsigned u){
    return __uint_as_float((u & 0x80000000u) ? (u ^ 0x80000000u) : ~u);
}
#define LDM_X4(r0,r1,r2,r3,addr) \
    asm volatile("ldmatrix.sync.aligned.m8n8.x4.shared.b16 {%0,%1,%2,%3}, [%4];" \
        :"=r"(r0),"=r"(r1),"=r"(r2),"=r"(r3):"r"(addr))
#define MMA_BF16(c0,c1,c2,c3,a0,a1,a2,a3,b0,b1) \
    asm volatile("mma.sync.aligned.m16n8k16.row.col.f32.bf16.bf16.f32 " \
        "{%0,%1,%2,%3},{%4,%5,%6,%7},{%8,%9},{%0,%1,%2,%3};" \
        :"+f"(c0),"+f"(c1),"+f"(c2),"+f"(c3) \
        :"r"(a0),"r"(a1),"r"(a2),"r"(a3),"r"(b0),"r"(b1))
#define CP_ASYNC16(dst,src) \
    asm volatile("cp.async.cg.shared.global [%0], [%1], 16;"::"r"(dst),"l"(src))
#define CP_COMMIT() asm volatile("cp.async.commit_group;":::"memory")
#define CP_WAIT1() asm volatile("cp.async.wait_group 1;":::"memory")

// ---------- prologue: enorm (serial-ascending FMA, verified rounding) + bf16 cvt ----------
__global__ void prep_kernel(const float* __restrict__ emb){
    int k = blockIdx.x*blockDim.x + threadIdx.x;
    const float4* p = (const float4*)(emb + (size_t)k*CDIM);
    __nv_bfloat162* q = (__nv_bfloat162*)(g_embf + (size_t)k*CDIM);
    float s = 0.f;
    #pragma unroll 8
    for(int i=0;i<64;++i){
        float4 v = p[i];
        s=__fmaf_rn(v.x,v.x,s); s=__fmaf_rn(v.y,v.y,s);
        s=__fmaf_rn(v.z,v.z,s); s=__fmaf_rn(v.w,v.w,s);
        q[i*2]   = __floats2bfloat162_rn(v.x, v.y);
        q[i*2+1] = __floats2bfloat162_rn(v.z, v.w);
    }
    g_enorm[k] = s;
}

// ---------- main: HMMA distance GEMM, 16 warps (4m x 4n), 32m x 32n per warp ----------
__global__ void __launch_bounds__(NTHREADS,1)
vq_main(const float* __restrict__ z, const float* __restrict__ emb){
    extern __shared__ char smem[];
    const uint32_t sb = smem_u32(smem);
    const int tid = threadIdx.x;
    const int lane = tid & 31, warp = tid >> 5;
    const int wm = warp & 3, wn = warp >> 2;      // 16 warps: 32m x 32n each
    const int g = lane >> 2, t4 = lane & 3;
    const int m0 = blockIdx.x*TILE_M;
    const int b = m0 >> 10, hw0 = m0 & 1023;

    unsigned* s_min = (unsigned*)(smem + OFF_SMIN);
    int* s_cnt = (int*)(smem + OFF_CNT);
    unsigned short* s_cand = (unsigned short*)(smem + OFF_CAND);
    if(tid < 128){ s_min[tid] = 0xFFFFFFFFu; s_cnt[tid] = 0; }

    // ---- z tile -> bf16 A (round-4 layout) ----
    const float* zb = z + (size_t)b*(CDIM*HWDIM) + hw0;
    #pragma unroll
    for(int i=0;i<16;++i){
        int v = tid + i*NTHREADS;
        int c = v >> 5, m4 = (v & 31)*4;
        float4 q = *(const float4*)(zb + (size_t)c*HWDIM + m4);
        *(__nv_bfloat16*)(smem + (m4+0)*ROWB + c*2) = __float2bfloat16_rn(q.x);
        *(__nv_bfloat16*)(smem + (m4+1)*ROWB + c*2) = __float2bfloat16_rn(q.y);
        *(__nv_bfloat16*)(smem + (m4+2)*ROWB + c*2) = __float2bfloat16_rn(q.z);
        *(__nv_bfloat16*)(smem + (m4+3)*ROWB + c*2) = __float2bfloat16_rn(q.w);
    }

    // ---- stage chunk 0 ----
    {
        const __nv_bfloat16* src = g_embf;
        #pragma unroll
        for(int i=0;i<8;++i){
            int seg = tid + i*NTHREADS;            // 4096 segs of 16B
            int n = seg >> 5, c16 = seg & 31;
            CP_ASYNC16(sb + OFF_BS + (uint32_t)(n*ROWB + c16*16),
                       src + (size_t)n*CDIM + c16*8);
        }
        CP_COMMIT();
    }

    // ldmatrix lane base addresses (round-4 per-warp shape)
    uint32_t a_base[2], b_base[2];
    #pragma unroll
    for(int mt=0;mt<2;++mt)
        a_base[mt] = sb + (uint32_t)((wm*32 + mt*16 + (lane & 15))*ROWB
                                     + ((lane >> 4) & 1)*16);
    #pragma unroll
    for(int nh=0;nh<2;++nh)
        b_base[nh] = sb + OFF_BS + (uint32_t)((wn*32 + nh*16 + ((lane >> 4) & 1)*8
                                     + (lane & 7))*ROWB + ((lane >> 3) & 1)*16);

    float rmv[2][2] = {{CUDART_INF_F, CUDART_INF_F},{CUDART_INF_F, CUDART_INF_F}};

    for(int ch=0; ch<NCHUNK; ++ch){
        const int buf = ch & 1;
        const int k0 = ch*CHUNK_N;
        if(ch+1 < NCHUNK){
            const __nv_bfloat16* src = g_embf + (size_t)(ch+1)*CHUNK_N*CDIM;
            const uint32_t bdst = sb + OFF_BS + (uint32_t)((buf^1)*BS_BUF);
            #pragma unroll
            for(int i=0;i<8;++i){
                int seg = tid + i*NTHREADS;
                int n = seg >> 5, c16 = seg & 31;
                CP_ASYNC16(bdst + (uint32_t)(n*ROWB + c16*16),
                           src + (size_t)n*CDIM + c16*8);
            }
        }
        CP_COMMIT();
        CP_WAIT1();
        __syncthreads();

        // ---- GEMM: 32m x 32n per warp, K=256 ----
        float acc[2][4][4];
        #pragma unroll
        for(int mt=0;mt<2;++mt)
            #pragma unroll
            for(int nt=0;nt<4;++nt)
                #pragma unroll
                for(int r=0;r<4;++r) acc[mt][nt][r] = 0.f;

        const uint32_t boff = (uint32_t)(buf*BS_BUF);
        #pragma unroll 4
        for(int ks=0; ks<16; ++ks){
            const uint32_t koff = (uint32_t)(ks*32);
            uint32_t a[2][4], bq[2][4];
            LDM_X4(a[0][0],a[0][1],a[0][2],a[0][3], a_base[0] + koff);
            LDM_X4(a[1][0],a[1][1],a[1][2],a[1][3], a_base[1] + koff);
            LDM_X4(bq[0][0],bq[0][1],bq[0][2],bq[0][3], b_base[0] + boff + koff);
            LDM_X4(bq[1][0],bq[1][1],bq[1][2],bq[1][3], b_base[1] + boff + koff);
            #pragma unroll
            for(int mt=0;mt<2;++mt)
                #pragma unroll
                for(int nt=0;nt<4;++nt)
                    MMA_BF16(acc[mt][nt][0],acc[mt][nt][1],acc[mt][nt][2],acc[mt][nt][3],
                             a[mt][0],a[mt][1],a[mt][2],a[mt][3],
                             bq[nt>>1][(nt&1)*2], bq[nt>>1][(nt&1)*2+1]);
        }

        // ---- phase a: d = enorm - 2*acc (in place), chunk min, record-improve atomic ----
        float en0[4], en1[4];
        #pragma unroll
        for(int nt=0;nt<4;++nt){
            int nb = k0 + wn*32 + nt*8 + 2*t4;
            en0[nt] = __ldg(&g_enorm[nb]); en1[nt] = __ldg(&g_enorm[nb+1]);
        }
        float cmin[2][2];
        #pragma unroll
        for(int mt=0;mt<2;++mt)
            #pragma unroll
            for(int h=0;h<2;++h){
                float cm = CUDART_INF_F;
                #pragma unroll
                for(int nt=0;nt<4;++nt){
                    float d0 = __fmaf_rn(-2.f, acc[mt][nt][2*h],   en0[nt]);
                    float d1 = __fmaf_rn(-2.f, acc[mt][nt][2*h+1], en1[nt]);
                    acc[mt][nt][2*h] = d0; acc[mt][nt][2*h+1] = d1;
                    if(d0 < cm) cm = d0;
                    if(d1 < cm) cm = d1;
                }
                cmin[mt][h] = cm;
                if(cm < rmv[mt][h]){
                    rmv[mt][h] = cm;
                    atomicMin(&s_min[wm*32 + mt*16 + g + h*8], fkey(cm));
                }
            }
        __syncthreads();

        // ---- phase b: push candidates within margin (skip if chunk can't qualify) ----
        #pragma unroll
        for(int mt=0;mt<2;++mt)
            #pragma unroll
            for(int h=0;h<2;++h){
                int m = wm*32 + mt*16 + g + h*8;
                float thr = funkey(s_min[m]) + MARGIN;
                if(cmin[mt][h] <= thr){
                    #pragma unroll
                    for(int nt=0;nt<4;++nt){
                        #pragma unroll
                        for(int q=0;q<2;++q){
                            float d = acc[mt][nt][2*h+q];
                            if(d <= thr){
                                int slot = atomicAdd(&s_cnt[m], 1);
                                if(slot < CAP)
                                    s_cand[m*CAP + slot] =
                                        (unsigned short)(k0 + wn*32 + nt*8 + 2*t4 + q);
                            }
                        }
                    }
                }
            }
    }
    __syncthreads();

    // ---- reload exact fp32 z tile into freed A/B smem ----
    float* zf = (float*)smem;
    #pragma unroll
    for(int i=0;i<16;++i){
        int v = tid + i*NTHREADS;
        int c = v >> 5, m4 = (v & 31)*4;
        float4 q = *(const float4*)(zb + (size_t)c*HWDIM + m4);
        zf[(m4+0)*257 + c] = q.x; zf[(m4+1)*257 + c] = q.y;
        zf[(m4+2)*257 + c] = q.z; zf[(m4+3)*257 + c] = q.w;
    }
    __syncthreads();

    // ---- exact fp32 rescore (serial-FMA rounding == reference path) ----
    if(tid < 128){
        float zn = 0.f;
        #pragma unroll 8
        for(int c=0;c<CDIM;++c){
            float v = zf[tid*257 + c];
            zn = __fmaf_rn(v, v, zn);
        }
        int cn = s_cnt[tid]; if(cn > CAP) cn = CAP;
        float best = CUDART_INF_F; int bi = 0x7FFFFFFF;
        for(int i=0;i<cn;++i){
            int k = (int)s_cand[tid*CAP + i];
            const float* er = emb + (size_t)k*CDIM;
            float acc2 = 0.f;
            #pragma unroll 8
            for(int c=0;c<CDIM;++c)
                acc2 = __fmaf_rn(zf[tid*257 + c], er[c], acc2);
            float dd = __fsub_rn(__fadd_rn(zn, g_enorm[k]), __fmul_rn(2.f, acc2));
            if(dd < best || (dd == best && k < bi)){ best = dd; bi = k; }
        }
        g_idx[m0 + tid] = bi;
    }
}

// ---------- outputs (passing since round 1) ----------
__global__ void output_kernel(const float* __restrict__ z, const float* __restrict__ emb,
                              float* __restrict__ out, int zq_off, int loss_off, int idx_off){
    int n = blockIdx.x, c = threadIdx.x;
    int b = n >> 10, hw = n & 1023;
    int idx = g_idx[n];
    float e  = emb[(size_t)idx*CDIM + c];
    float zv = z[(size_t)b*(CDIM*HWDIM) + (size_t)c*HWDIM + hw];
    float dq = __fsub_rn(e, zv);
    float zq = __fadd_rn(zv, dq);
    float d2 = __fmul_rn(dq, dq);
    float loss = __fadd_rn(__fmul_rn(0.25f, d2), d2);
    if(zq_off  >= 0) out[(size_t)zq_off + (size_t)b*(CDIM*HWDIM) + (size_t)c*HWDIM + hw] = zq;
    if(loss_off>= 0) out[(size_t)loss_off + (size_t)n*CDIM + c] = loss;
    if(idx_off >= 0 && c == 0) out[(size_t)idx_off + n] = (float)idx;
}

extern "C" void kernel_launch(void* const* d_in, const int* in_sizes, int n_in,
                              void* d_out, int out_size){
    const float* z   = (const float*)d_in[0];
    const float* emb = (const float*)d_in[1];
    if(n_in >= 2 && in_sizes[0] == K_CODES*CDIM && in_sizes[1] == ZQ_ELEMS){
        z = (const float*)d_in[1]; emb = (const float*)d_in[0];
    }
    float* out = (float*)d_out;

    prep_kernel<<<K_CODES/256, 256>>>(emb);

    cudaFuncSetAttribute(vq_main, cudaFuncAttributeMaxDynamicSharedMemorySize, SMEM_TOTAL);
    vq_main<<<N_TOK/TILE_M, NTHREADS, SMEM_TOTAL>>>(z, emb);

    int zq_off=-1, loss_off=-1, idx_off=-1;
    if(out_size == 2*ZQ_ELEMS + IX_ELEMS){ zq_off=0; loss_off=ZQ_ELEMS; idx_off=2*ZQ_ELEMS; }
    else if(out_size == 2*ZQ_ELEMS){ zq_off=0; loss_off=ZQ_ELEMS; }
    else if(out_size == ZQ_ELEMS + IX_ELEMS){ zq_off=0; idx_off=ZQ_ELEMS; }
    else if(out_size == ZQ_ELEMS){ zq_off=0; }
    else if(out_size == IX_ELEMS){ idx_off=0; }
    else{
        int rem = out_size;
        if(rem >= ZQ_ELEMS){ zq_off=0; rem -= ZQ_ELEMS; }
        if(rem >= ZQ_ELEMS){ loss_off=ZQ_ELEMS; rem -= ZQ_ELEMS; }
        if(rem >= IX_ELEMS){ idx_off = out_size - IX_ELEMS; }
    }
    output_kernel<<<N_TOK, 256>>>(z, emb, out, zq_off, loss_off, idx_off);
}